// round 4
// baseline (speedup 1.0000x reference)
#include <cuda_runtime.h>
#include <math.h>

#define K_DIM 2144     // 64 + 2016 + 64
#define M_ROWS 20000   // 400 sequences * 50 segments
#define M_PAD 20096    // 157 * 128
#define NSEG 50
#define GATES 512

// Scratch (device globals: allocation-free). Padded rows stay zero (.bss).
__device__ float g_seq[(size_t)M_PAD * K_DIM];     // logsig features, row-major [M, 2144]
__device__ float g_xproj[(size_t)M_PAD * GATES];   // x @ W_ih^T + b_ih + b_hh

// ---------------------------------------------------------------------------
// Kernel 1: segment log-signature.
// x: (B=16, C=64, T=200, V=25). n = b*25+v, segment s uses t = 4s..4s+3.
// With increments a=p1-p0, b=p2-p1, c=p3-p2:
//   S2 = a (x) b + (a+b) (x) c ,  A = 0.5*(S2 - S2^T)
//   levy(i<j) = 0.5*(a_i b_j - a_j b_i + (a_i+b_i) c_j - (a_j+b_j) c_i)
// seq row m = n*50+s : [ lvl1(64) | levy(2016) | start(64) ]
// ---------------------------------------------------------------------------
__global__ void logsig_kernel(const float* __restrict__ x) {
    const int s = blockIdx.x;   // 0..49
    const int b = blockIdx.y;   // 0..15
    __shared__ float sa[64 * 25];
    __shared__ float sb[64 * 25];
    __shared__ float sc[64 * 25];
    const int tid = threadIdx.x;

    // Load 4 time points per (c, v), compute increments, write lvl1 + start.
    for (int item = tid; item < 64 * 25; item += 256) {
        const int c = item / 25;
        const int v = item % 25;
        const long base = ((long)(b * 64 + c) * 200 + 4 * s) * 25 + v;
        const float p0 = x[base];
        const float p1 = x[base + 25];
        const float p2 = x[base + 50];
        const float p3 = x[base + 75];
        sa[item] = p1 - p0;
        sb[item] = p2 - p1;
        sc[item] = p3 - p2;
        const long m = (long)(b * 25 + v) * NSEG + s;
        g_seq[m * K_DIM + c]        = p3 - p0;  // lvl1
        g_seq[m * K_DIM + 2080 + c] = p0;       // start
    }
    __syncthreads();

    // Levy area terms: loop v so writes along k are coalesced.
    for (int v = 0; v < 25; v++) {
        const long m = (long)(b * 25 + v) * NSEG + s;
        float* __restrict__ dst = &g_seq[m * K_DIM + 64];
        int i = 0, off = 0;  // row i starts at linear offset off = 63*i - i*(i-1)/2
        for (int k = tid; k < 2016; k += 256) {
            while (off + (63 - i) <= k) { off += 63 - i; i++; }
            const int j = i + 1 + (k - off);
            const float ai = sa[i * 25 + v], aj = sa[j * 25 + v];
            const float bi = sb[i * 25 + v], bj = sb[j * 25 + v];
            const float ci = sc[i * 25 + v], cj = sc[j * 25 + v];
            dst[k] = 0.5f * (ai * bj - aj * bi + (ai + bi) * cj - (aj + bj) * ci);
        }
    }
}

// ---------------------------------------------------------------------------
// Kernel 2: x_proj = seq @ W_ih^T + (b_ih + b_hh).
// A = g_seq [M_PAD x 2144], B = W_ih [512 x 2144] (both K-contiguous, "NT").
// 128x128x16 tiles, 256 threads, 8x8 per thread. M padded -> no bounds checks.
// ---------------------------------------------------------------------------
__global__ __launch_bounds__(256, 2) void gemm_kernel(
    const float* __restrict__ B,
    const float* __restrict__ b_ih,
    const float* __restrict__ b_hh)
{
    __shared__ __align__(16) float As[16][132];
    __shared__ __align__(16) float Bs[16][132];
    const float* __restrict__ A = g_seq;

    const int bm = blockIdx.x * 128;
    const int bn = blockIdx.y * 128;
    const int tid = threadIdx.x;
    const int tx = tid & 15;
    const int ty = tid >> 4;

    float acc[8][8];
#pragma unroll
    for (int i = 0; i < 8; i++)
#pragma unroll
        for (int j = 0; j < 8; j++) acc[i][j] = 0.f;

    for (int k0 = 0; k0 < K_DIM; k0 += 16) {
#pragma unroll
        for (int it = 0; it < 2; it++) {
            const int q = tid + it * 256;           // 512 float4 per tile
            const int row = q >> 2;                 // 0..127
            const int kq = (q & 3) * 4;             // 0,4,8,12
            const float4 av = *(const float4*)&A[(size_t)(bm + row) * K_DIM + k0 + kq];
            As[kq + 0][row] = av.x; As[kq + 1][row] = av.y;
            As[kq + 2][row] = av.z; As[kq + 3][row] = av.w;
            const float4 bv = *(const float4*)&B[(size_t)(bn + row) * K_DIM + k0 + kq];
            Bs[kq + 0][row] = bv.x; Bs[kq + 1][row] = bv.y;
            Bs[kq + 2][row] = bv.z; Bs[kq + 3][row] = bv.w;
        }
        __syncthreads();

#pragma unroll
        for (int k = 0; k < 16; k++) {
            float ar[8], br[8];
            *(float4*)&ar[0] = *(const float4*)&As[k][ty * 8];
            *(float4*)&ar[4] = *(const float4*)&As[k][ty * 8 + 4];
            *(float4*)&br[0] = *(const float4*)&Bs[k][tx * 8];
            *(float4*)&br[4] = *(const float4*)&Bs[k][tx * 8 + 4];
#pragma unroll
            for (int i = 0; i < 8; i++)
#pragma unroll
                for (int j = 0; j < 8; j++)
                    acc[i][j] += ar[i] * br[j];
        }
        __syncthreads();
    }

#pragma unroll
    for (int i = 0; i < 8; i++) {
        const int row = bm + ty * 8 + i;
#pragma unroll
        for (int j = 0; j < 8; j++) {
            const int col = bn + tx * 8 + j;
            g_xproj[(size_t)row * GATES + col] = acc[i][j] + b_ih[col] + b_hh[col];
        }
    }
}

// ---------------------------------------------------------------------------
// Kernel 3: LSTM recurrence. 100 blocks x 4 sequences, 512 threads.
// Thread g computes gate row g for its 4 sequences:
//   W_hh[g][0:64]  cached in registers (loaded once)
//   W_hh[g][64:128] re-read from L2 each step (fits L2, stays hot)
// Pointwise phase: thread (sq = tid>>7, j = tid&127) owns c in a register.
// ---------------------------------------------------------------------------
__device__ __forceinline__ float sigmoidf_(float v) {
    return 1.f / (1.f + expf(-v));
}

__global__ __launch_bounds__(512, 1) void lstm_kernel(
    const float* __restrict__ Whh,
    float* __restrict__ out)
{
    __shared__ float h_sh[4 * 128];
    __shared__ float gates_sh[4 * 512];

    const int tid = threadIdx.x;
    const int n0 = blockIdx.x * 4;

    // Register-cache lower 64 recurrent weights of this gate row.
    float wreg[64];
    {
        const float4* wp = (const float4*)(Whh + tid * 128);
#pragma unroll
        for (int i = 0; i < 16; i++) {
            const float4 t = wp[i];
            wreg[i * 4 + 0] = t.x; wreg[i * 4 + 1] = t.y;
            wreg[i * 4 + 2] = t.z; wreg[i * 4 + 3] = t.w;
        }
    }
    const float* __restrict__ wgu = Whh + tid * 128 + 64;  // upper half (global/L2)

    h_sh[tid] = 0.f;  // 512 threads cover all 4*128 h entries
    const int sq = tid >> 7;
    const int j  = tid & 127;
    float creg = 0.f;
    const int n_pw = n0 + sq;
    const int bb = n_pw / 25;
    const int vv = n_pw % 25;
    const long outbase = ((long)(bb * 128 + j) * 50) * 25 + vv;
    __syncthreads();

    for (int s = 0; s < NSEG; s++) {
        float acc0 = g_xproj[(size_t)((n0 + 0) * 50 + s) * GATES + tid];
        float acc1 = g_xproj[(size_t)((n0 + 1) * 50 + s) * GATES + tid];
        float acc2 = g_xproj[(size_t)((n0 + 2) * 50 + s) * GATES + tid];
        float acc3 = g_xproj[(size_t)((n0 + 3) * 50 + s) * GATES + tid];

        // lower 64 k: weights in registers
#pragma unroll
        for (int k = 0; k < 64; k += 4) {
            const float4 h0 = *(const float4*)&h_sh[0 * 128 + k];
            const float4 h1 = *(const float4*)&h_sh[1 * 128 + k];
            const float4 h2 = *(const float4*)&h_sh[2 * 128 + k];
            const float4 h3 = *(const float4*)&h_sh[3 * 128 + k];
            const float w0 = wreg[k], w1 = wreg[k + 1], w2 = wreg[k + 2], w3 = wreg[k + 3];
            acc0 += w0 * h0.x + w1 * h0.y + w2 * h0.z + w3 * h0.w;
            acc1 += w0 * h1.x + w1 * h1.y + w2 * h1.z + w3 * h1.w;
            acc2 += w0 * h2.x + w1 * h2.y + w2 * h2.z + w3 * h2.w;
            acc3 += w0 * h3.x + w1 * h3.y + w2 * h3.z + w3 * h3.w;
        }
        // upper 64 k: weights from L2 (256 KB working set, fully cached)
#pragma unroll
        for (int k = 0; k < 64; k += 4) {
            const float4 w4 = *(const float4*)&wgu[k];
            const float4 h0 = *(const float4*)&h_sh[0 * 128 + 64 + k];
            const float4 h1 = *(const float4*)&h_sh[1 * 128 + 64 + k];
            const float4 h2 = *(const float4*)&h_sh[2 * 128 + 64 + k];
            const float4 h3 = *(const float4*)&h_sh[3 * 128 + 64 + k];
            acc0 += w4.x * h0.x + w4.y * h0.y + w4.z * h0.z + w4.w * h0.w;
            acc1 += w4.x * h1.x + w4.y * h1.y + w4.z * h1.z + w4.w * h1.w;
            acc2 += w4.x * h2.x + w4.y * h2.y + w4.z * h2.z + w4.w * h2.w;
            acc3 += w4.x * h3.x + w4.y * h3.y + w4.z * h3.z + w4.w * h3.w;
        }
        gates_sh[0 * 512 + tid] = acc0;
        gates_sh[1 * 512 + tid] = acc1;
        gates_sh[2 * 512 + tid] = acc2;
        gates_sh[3 * 512 + tid] = acc3;
        __syncthreads();

        // pointwise: gates layout [i | f | g | o], 128 each
        const float gi = gates_sh[sq * 512 + j];
        const float gf = gates_sh[sq * 512 + 128 + j];
        const float gg = gates_sh[sq * 512 + 256 + j];
        const float go = gates_sh[sq * 512 + 384 + j];
        creg = sigmoidf_(gf) * creg + sigmoidf_(gi) * tanhf(gg);
        const float h = sigmoidf_(go) * tanhf(creg);
        h_sh[sq * 128 + j] = h;
        out[outbase + (long)s * 25] = h;   // out[b, j, s, v]
        __syncthreads();
    }
}

// ---------------------------------------------------------------------------
extern "C" void kernel_launch(void* const* d_in, const int* in_sizes, int n_in,
                              void* d_out, int out_size) {
    const float* x    = (const float*)d_in[0];  // (16,64,200,25)
    const float* W_ih = (const float*)d_in[1];  // (512,2144)
    const float* W_hh = (const float*)d_in[2];  // (512,128)
    const float* b_ih = (const float*)d_in[3];  // (512)
    const float* b_hh = (const float*)d_in[4];  // (512)
    float* out = (float*)d_out;                 // (16,128,50,25)
    (void)in_sizes; (void)n_in; (void)out_size;

    dim3 gl(NSEG, 16);
    logsig_kernel<<<gl, 256, 0, 0>>>(x);

    dim3 gg(M_PAD / 128, GATES / 128);          // 157 x 4
    gemm_kernel<<<gg, 256, 0, 0>>>(W_ih, b_ih, b_hh);

    lstm_kernel<<<100, 512, 0, 0>>>(W_hh, out);
}

// round 6
// speedup vs baseline: 3.2074x; 3.2074x over previous
#include <cuda_runtime.h>
#include <cuda_bf16.h>
#include <math.h>
#include <stdint.h>

#define K_DIM 2144     // 64 + 2016 + 64
#define M_ROWS 20000   // 400 sequences * 50 segments
#define M_PAD 20096    // 157 * 128
#define NSEG 50
#define GATES 512

// Scratch (device globals: allocation-free, zero-initialized .bss).
// Padded rows [20000, 20096) stay zero forever.
__device__ __nv_bfloat16 g_Ahi[(size_t)M_PAD * K_DIM];  // logsig features hi
__device__ __nv_bfloat16 g_Alo[(size_t)M_PAD * K_DIM];  // logsig features lo
__device__ __nv_bfloat16 g_Bhi[(size_t)GATES * K_DIM];  // W_ih hi
__device__ __nv_bfloat16 g_Blo[(size_t)GATES * K_DIM];  // W_ih lo
__device__ float g_xproj[(size_t)M_PAD * GATES];        // seq @ W_ih^T + b_ih + b_hh

__device__ __forceinline__ void split_bf16(float x, __nv_bfloat16& hi, __nv_bfloat16& lo) {
    hi = __float2bfloat16_rn(x);
    lo = __float2bfloat16_rn(x - __bfloat162float(hi));
}

// ---------------------------------------------------------------------------
// Kernel 1: segment log-signature -> split-bf16 feature rows.
// x: (B=16, C=64, T=200, V=25). n = b*25+v, segment s uses t = 4s..4s+3.
// increments a=p1-p0, b=p2-p1, c=p3-p2:
//   levy(i<j) = 0.5*(a_i b_j - a_j b_i + (a_i+b_i) c_j - (a_j+b_j) c_i)
// row m = n*50+s : [ lvl1(64) | levy(2016) | start(64) ]
// ---------------------------------------------------------------------------
__global__ void logsig_kernel(const float* __restrict__ x) {
    const int s = blockIdx.x;   // 0..49
    const int b = blockIdx.y;   // 0..15
    __shared__ float sa[64 * 25];
    __shared__ float sb[64 * 25];
    __shared__ float sc[64 * 25];
    const int tid = threadIdx.x;

    for (int item = tid; item < 64 * 25; item += 256) {
        const int c = item / 25;
        const int v = item % 25;
        const long base = ((long)(b * 64 + c) * 200 + 4 * s) * 25 + v;
        const float p0 = x[base];
        const float p1 = x[base + 25];
        const float p2 = x[base + 50];
        const float p3 = x[base + 75];
        sa[item] = p1 - p0;
        sb[item] = p2 - p1;
        sc[item] = p3 - p2;
        const size_t m = (size_t)(b * 25 + v) * NSEG + s;
        split_bf16(p3 - p0, g_Ahi[m * K_DIM + c],        g_Alo[m * K_DIM + c]);
        split_bf16(p0,      g_Ahi[m * K_DIM + 2080 + c], g_Alo[m * K_DIM + 2080 + c]);
    }
    __syncthreads();

    // Triangular (i,j) indices for this thread's 8 strided k values: computed ONCE.
    int ii[8], jj[8];
    {
        int i = 0, off = 0;  // row i starts at off = 63*i - i*(i-1)/2
        for (int u = 0; u < 8; ++u) {
            const int k = tid + (u << 8);
            if (k < 2016) {
                while (off + (63 - i) <= k) { off += 63 - i; ++i; }
                ii[u] = i; jj[u] = i + 1 + (k - off);
            } else { ii[u] = 0; jj[u] = 1; }
        }
    }

    for (int v = 0; v < 25; ++v) {
        const size_t m = (size_t)(b * 25 + v) * NSEG + s;
        __nv_bfloat16* __restrict__ dh = g_Ahi + m * K_DIM + 64;
        __nv_bfloat16* __restrict__ dl = g_Alo + m * K_DIM + 64;
#pragma unroll
        for (int u = 0; u < 8; ++u) {
            const int k = tid + (u << 8);
            if (k < 2016) {
                const int i = ii[u], j = jj[u];
                const float ai = sa[i * 25 + v], aj = sa[j * 25 + v];
                const float bi = sb[i * 25 + v], bj = sb[j * 25 + v];
                const float ci = sc[i * 25 + v], cj = sc[j * 25 + v];
                const float val = 0.5f * (ai * bj - aj * bi + (ai + bi) * cj - (aj + bj) * ci);
                split_bf16(val, dh[k], dl[k]);
            }
        }
    }
}

// ---------------------------------------------------------------------------
// Kernel 1b: split W_ih into bf16 hi/lo.
// ---------------------------------------------------------------------------
__global__ void wconv_kernel(const float* __restrict__ W) {
    const int idx = blockIdx.x * 256 + threadIdx.x;
    if (idx < GATES * K_DIM) {
        split_bf16(W[idx], g_Bhi[idx], g_Blo[idx]);
    }
}

// ---------------------------------------------------------------------------
// Kernel 2: x_proj = seq @ W_ih^T + bias via split-bf16 HMMA.
// acc = Ahi*Bhi + Ahi*Blo + Alo*Bhi  (fp32 accumulate; lo*lo dropped ~2^-16).
// Tiles: BM=128, BN=128, BK=16; 256 threads = 8 warps, warp tile 32x64.
// 2-stage cp.async pipeline; swizzled smem + ldmatrix.x4.
// ---------------------------------------------------------------------------
__device__ __forceinline__ void cp16(void* dst, const void* src) {
    const uint32_t d = (uint32_t)__cvta_generic_to_shared(dst);
    asm volatile("cp.async.cg.shared.global [%0], [%1], 16;\n" :: "r"(d), "l"(src));
}
__device__ __forceinline__ void ldsm4(uint32_t* r, const __nv_bfloat16* p) {
    const uint32_t a = (uint32_t)__cvta_generic_to_shared(p);
    asm volatile("ldmatrix.sync.aligned.m8n8.x4.shared.b16 {%0,%1,%2,%3}, [%4];"
                 : "=r"(r[0]), "=r"(r[1]), "=r"(r[2]), "=r"(r[3]) : "r"(a));
}
__device__ __forceinline__ void mma16816(float* c, const uint32_t* a, uint32_t b0, uint32_t b1) {
    asm volatile("mma.sync.aligned.m16n8k16.row.col.f32.bf16.bf16.f32 "
                 "{%0,%1,%2,%3}, {%4,%5,%6,%7}, {%8,%9}, {%0,%1,%2,%3};"
                 : "+f"(c[0]), "+f"(c[1]), "+f"(c[2]), "+f"(c[3])
                 : "r"(a[0]), "r"(a[1]), "r"(a[2]), "r"(a[3]), "r"(b0), "r"(b1));
}

#define NIT (K_DIM / 16)   // 134

__global__ __launch_bounds__(256, 1) void gemm_kernel(
    const float* __restrict__ b_ih,
    const float* __restrict__ b_hh)
{
    // [stage][hi/lo][128 rows x 16 cols], swizzled 16B chunks. 32 KB total.
    __shared__ __align__(128) __nv_bfloat16 sA[2][2][128 * 16];
    __shared__ __align__(128) __nv_bfloat16 sB[2][2][128 * 16];

    const int tid = threadIdx.x;
    const int bm = blockIdx.x * 128;
    const int bn = blockIdx.y * 128;

    // --- prefetch addressing (1 x 16B chunk per thread per array per stage) ---
    const int prow = tid >> 1;                 // 0..127
    const int pch  = tid & 1;                  // logical chunk
    const int psc  = pch ^ ((prow >> 2) & 1);  // physical (swizzled) chunk
    const int psoff = prow * 16 + psc * 8;     // bf16 elems
    const size_t aoff = (size_t)(bm + prow) * K_DIM + pch * 8;
    const size_t boff = (size_t)(bn + prow) * K_DIM + pch * 8;

    // --- ldmatrix addressing (per-iter invariant) ---
    const int lane = tid & 31;
    const int warp = tid >> 5;
    const int wm = warp >> 1;                  // 0..3  (m: wm*32)
    const int wn = warp & 1;                   // 0..1  (n: wn*64)
    int aoffs[2];
#pragma unroll
    for (int mf = 0; mf < 2; ++mf) {
        const int r = wm * 32 + mf * 16 + (lane & 15);
        const int c = lane >> 4;
        aoffs[mf] = r * 16 + (c ^ ((r >> 2) & 1)) * 8;
    }
    int boffs[4];
#pragma unroll
    for (int ng = 0; ng < 4; ++ng) {
        const int r = wn * 64 + ng * 16 + ((lane & 7) | ((lane >> 4) << 3));
        const int c = (lane >> 3) & 1;
        boffs[ng] = r * 16 + (c ^ ((r >> 2) & 1)) * 8;
    }

    float acc[2][8][4];
#pragma unroll
    for (int mf = 0; mf < 2; ++mf)
#pragma unroll
        for (int n8 = 0; n8 < 8; ++n8)
#pragma unroll
            for (int q = 0; q < 4; ++q) acc[mf][n8][q] = 0.f;

    // stage 0 prefetch
    cp16(&sA[0][0][psoff], g_Ahi + aoff);
    cp16(&sA[0][1][psoff], g_Alo + aoff);
    cp16(&sB[0][0][psoff], g_Bhi + boff);
    cp16(&sB[0][1][psoff], g_Blo + boff);
    asm volatile("cp.async.commit_group;\n" ::);

    for (int it = 0; it < NIT; ++it) {
        if (it + 1 < NIT) {
            const int ns = (it + 1) & 1;
            const size_t kk = (size_t)(it + 1) * 16;
            cp16(&sA[ns][0][psoff], g_Ahi + aoff + kk);
            cp16(&sA[ns][1][psoff], g_Alo + aoff + kk);
            cp16(&sB[ns][0][psoff], g_Bhi + boff + kk);
            cp16(&sB[ns][1][psoff], g_Blo + boff + kk);
        }
        asm volatile("cp.async.commit_group;\n" ::);
        asm volatile("cp.async.wait_group 1;\n" ::);
        __syncthreads();

        const int s = it & 1;
        uint32_t ahi[2][4], alo[2][4], bhi[4][4], blo[4][4];
#pragma unroll
        for (int mf = 0; mf < 2; ++mf) {
            ldsm4(ahi[mf], &sA[s][0][aoffs[mf]]);
            ldsm4(alo[mf], &sA[s][1][aoffs[mf]]);
        }
#pragma unroll
        for (int ng = 0; ng < 4; ++ng) {
            ldsm4(bhi[ng], &sB[s][0][boffs[ng]]);
            ldsm4(blo[ng], &sB[s][1][boffs[ng]]);
        }
#pragma unroll
        for (int mf = 0; mf < 2; ++mf)
#pragma unroll
            for (int ng = 0; ng < 4; ++ng)
#pragma unroll
                for (int h = 0; h < 2; ++h) {
                    float* c = acc[mf][ng * 2 + h];
                    mma16816(c, ahi[mf], bhi[ng][2 * h], bhi[ng][2 * h + 1]);
                    mma16816(c, ahi[mf], blo[ng][2 * h], blo[ng][2 * h + 1]);
                    mma16816(c, alo[mf], bhi[ng][2 * h], bhi[ng][2 * h + 1]);
                }
        __syncthreads();
    }

    // epilogue: c-frag lane mapping (m = l/4 (+8), n = 2*(l%4) (+1))
    const int qr = lane >> 2;
    const int qc = (lane & 3) * 2;
#pragma unroll
    for (int mf = 0; mf < 2; ++mf) {
#pragma unroll
        for (int n8 = 0; n8 < 8; ++n8) {
            const int m0 = bm + wm * 32 + mf * 16 + qr;
            const int n0 = bn + wn * 64 + n8 * 8 + qc;
            const float bias0 = b_ih[n0] + b_hh[n0];
            const float bias1 = b_ih[n0 + 1] + b_hh[n0 + 1];
            const float* c = acc[mf][n8];
            g_xproj[(size_t)m0 * GATES + n0]           = c[0] + bias0;
            g_xproj[(size_t)m0 * GATES + n0 + 1]       = c[1] + bias1;
            g_xproj[(size_t)(m0 + 8) * GATES + n0]     = c[2] + bias0;
            g_xproj[(size_t)(m0 + 8) * GATES + n0 + 1] = c[3] + bias1;
        }
    }
}

// ---------------------------------------------------------------------------
// Kernel 3: LSTM recurrence (unchanged from R3). 100 blocks x 4 sequences.
// ---------------------------------------------------------------------------
__device__ __forceinline__ float sigmoidf_(float v) {
    return 1.f / (1.f + expf(-v));
}

__global__ __launch_bounds__(512, 1) void lstm_kernel(
    const float* __restrict__ Whh,
    float* __restrict__ out)
{
    __shared__ float h_sh[4 * 128];
    __shared__ float gates_sh[4 * 512];

    const int tid = threadIdx.x;
    const int n0 = blockIdx.x * 4;

    float wreg[64];
    {
        const float4* wp = (const float4*)(Whh + tid * 128);
#pragma unroll
        for (int i = 0; i < 16; i++) {
            const float4 t = wp[i];
            wreg[i * 4 + 0] = t.x; wreg[i * 4 + 1] = t.y;
            wreg[i * 4 + 2] = t.z; wreg[i * 4 + 3] = t.w;
        }
    }
    const float* __restrict__ wgu = Whh + tid * 128 + 64;

    h_sh[tid] = 0.f;
    const int sq = tid >> 7;
    const int j  = tid & 127;
    float creg = 0.f;
    const int n_pw = n0 + sq;
    const int bb = n_pw / 25;
    const int vv = n_pw % 25;
    const long outbase = ((long)(bb * 128 + j) * 50) * 25 + vv;
    __syncthreads();

    for (int s = 0; s < NSEG; s++) {
        float acc0 = g_xproj[(size_t)((n0 + 0) * 50 + s) * GATES + tid];
        float acc1 = g_xproj[(size_t)((n0 + 1) * 50 + s) * GATES + tid];
        float acc2 = g_xproj[(size_t)((n0 + 2) * 50 + s) * GATES + tid];
        float acc3 = g_xproj[(size_t)((n0 + 3) * 50 + s) * GATES + tid];

#pragma unroll
        for (int k = 0; k < 64; k += 4) {
            const float4 h0 = *(const float4*)&h_sh[0 * 128 + k];
            const float4 h1 = *(const float4*)&h_sh[1 * 128 + k];
            const float4 h2 = *(const float4*)&h_sh[2 * 128 + k];
            const float4 h3 = *(const float4*)&h_sh[3 * 128 + k];
            const float w0 = wreg[k], w1 = wreg[k + 1], w2 = wreg[k + 2], w3 = wreg[k + 3];
            acc0 += w0 * h0.x + w1 * h0.y + w2 * h0.z + w3 * h0.w;
            acc1 += w0 * h1.x + w1 * h1.y + w2 * h1.z + w3 * h1.w;
            acc2 += w0 * h2.x + w1 * h2.y + w2 * h2.z + w3 * h2.w;
            acc3 += w0 * h3.x + w1 * h3.y + w2 * h3.z + w3 * h3.w;
        }
#pragma unroll
        for (int k = 0; k < 64; k += 4) {
            const float4 w4 = *(const float4*)&wgu[k];
            const float4 h0 = *(const float4*)&h_sh[0 * 128 + 64 + k];
            const float4 h1 = *(const float4*)&h_sh[1 * 128 + 64 + k];
            const float4 h2 = *(const float4*)&h_sh[2 * 128 + 64 + k];
            const float4 h3 = *(const float4*)&h_sh[3 * 128 + 64 + k];
            acc0 += w4.x * h0.x + w4.y * h0.y + w4.z * h0.z + w4.w * h0.w;
            acc1 += w4.x * h1.x + w4.y * h1.y + w4.z * h1.z + w4.w * h1.w;
            acc2 += w4.x * h2.x + w4.y * h2.y + w4.z * h2.z + w4.w * h2.w;
            acc3 += w4.x * h3.x + w4.y * h3.y + w4.z * h3.z + w4.w * h3.w;
        }
        gates_sh[0 * 512 + tid] = acc0;
        gates_sh[1 * 512 + tid] = acc1;
        gates_sh[2 * 512 + tid] = acc2;
        gates_sh[3 * 512 + tid] = acc3;
        __syncthreads();

        const float gi = gates_sh[sq * 512 + j];
        const float gf = gates_sh[sq * 512 + 128 + j];
        const float gg = gates_sh[sq * 512 + 256 + j];
        const float go = gates_sh[sq * 512 + 384 + j];
        creg = sigmoidf_(gf) * creg + sigmoidf_(gi) * tanhf(gg);
        const float h = sigmoidf_(go) * tanhf(creg);
        h_sh[sq * 128 + j] = h;
        out[outbase + (long)s * 25] = h;
        __syncthreads();
    }
}

// ---------------------------------------------------------------------------
extern "C" void kernel_launch(void* const* d_in, const int* in_sizes, int n_in,
                              void* d_out, int out_size) {
    const float* x    = (const float*)d_in[0];  // (16,64,200,25)
    const float* W_ih = (const float*)d_in[1];  // (512,2144)
    const float* W_hh = (const float*)d_in[2];  // (512,128)
    const float* b_ih = (const float*)d_in[3];  // (512)
    const float* b_hh = (const float*)d_in[4];  // (512)
    float* out = (float*)d_out;                 // (16,128,50,25)
    (void)in_sizes; (void)n_in; (void)out_size;

    dim3 gl(NSEG, 16);
    logsig_kernel<<<gl, 256, 0, 0>>>(x);

    wconv_kernel<<<(GATES * K_DIM + 255) / 256, 256, 0, 0>>>(W_ih);

    dim3 gg(M_PAD / 128, GATES / 128);          // 157 x 4
    gemm_kernel<<<gg, 256, 0, 0>>>(b_ih, b_hh);

    lstm_kernel<<<100, 512, 0, 0>>>(W_hh, out);
}

// round 7
// speedup vs baseline: 3.3799x; 1.0538x over previous
#include <cuda_runtime.h>
#include <cuda_bf16.h>
#include <math.h>
#include <stdint.h>

#define K_DIM 2144     // 64 + 2016 + 64
#define M_ROWS 20000   // 400 sequences * 50 segments
#define M_PAD 20096    // 157 * 128
#define NSEG 50
#define GATES 512

// Scratch (device globals: allocation-free, zero-initialized .bss).
// Padded rows [20000, 20096) stay zero forever.
__device__ __nv_bfloat16 g_Ahi[(size_t)M_PAD * K_DIM];  // logsig features hi
__device__ __nv_bfloat16 g_Alo[(size_t)M_PAD * K_DIM];  // logsig features lo
__device__ __nv_bfloat16 g_Bhi[(size_t)GATES * K_DIM];  // W_ih hi
__device__ __nv_bfloat16 g_Blo[(size_t)GATES * K_DIM];  // W_ih lo
__device__ float g_xproj[(size_t)M_PAD * GATES];        // seq @ W_ih^T + b_ih + b_hh

__device__ __forceinline__ void split_bf16(float x, __nv_bfloat16& hi, __nv_bfloat16& lo) {
    hi = __float2bfloat16_rn(x);
    lo = __float2bfloat16_rn(x - __bfloat162float(hi));
}

// ---------------------------------------------------------------------------
// Kernel 1: segment log-signature -> split-bf16 feature rows.
// ---------------------------------------------------------------------------
__global__ void logsig_kernel(const float* __restrict__ x) {
    const int s = blockIdx.x;   // 0..49
    const int b = blockIdx.y;   // 0..15
    __shared__ float sa[64 * 25];
    __shared__ float sb[64 * 25];
    __shared__ float sc[64 * 25];
    const int tid = threadIdx.x;

    for (int item = tid; item < 64 * 25; item += 256) {
        const int c = item / 25;
        const int v = item % 25;
        const long base = ((long)(b * 64 + c) * 200 + 4 * s) * 25 + v;
        const float p0 = x[base];
        const float p1 = x[base + 25];
        const float p2 = x[base + 50];
        const float p3 = x[base + 75];
        sa[item] = p1 - p0;
        sb[item] = p2 - p1;
        sc[item] = p3 - p2;
        const size_t m = (size_t)(b * 25 + v) * NSEG + s;
        split_bf16(p3 - p0, g_Ahi[m * K_DIM + c],        g_Alo[m * K_DIM + c]);
        split_bf16(p0,      g_Ahi[m * K_DIM + 2080 + c], g_Alo[m * K_DIM + 2080 + c]);
    }
    __syncthreads();

    // Triangular (i,j) indices for this thread's 8 strided k values: computed ONCE.
    int ii[8], jj[8];
    {
        int i = 0, off = 0;  // row i starts at off = 63*i - i*(i-1)/2
        for (int u = 0; u < 8; ++u) {
            const int k = tid + (u << 8);
            if (k < 2016) {
                while (off + (63 - i) <= k) { off += 63 - i; ++i; }
                ii[u] = i; jj[u] = i + 1 + (k - off);
            } else { ii[u] = 0; jj[u] = 1; }
        }
    }

    for (int v = 0; v < 25; ++v) {
        const size_t m = (size_t)(b * 25 + v) * NSEG + s;
        __nv_bfloat16* __restrict__ dh = g_Ahi + m * K_DIM + 64;
        __nv_bfloat16* __restrict__ dl = g_Alo + m * K_DIM + 64;
#pragma unroll
        for (int u = 0; u < 8; ++u) {
            const int k = tid + (u << 8);
            if (k < 2016) {
                const int i = ii[u], j = jj[u];
                const float ai = sa[i * 25 + v], aj = sa[j * 25 + v];
                const float bi = sb[i * 25 + v], bj = sb[j * 25 + v];
                const float ci = sc[i * 25 + v], cj = sc[j * 25 + v];
                const float val = 0.5f * (ai * bj - aj * bi + (ai + bi) * cj - (aj + bj) * ci);
                split_bf16(val, dh[k], dl[k]);
            }
        }
    }
}

// ---------------------------------------------------------------------------
// Kernel 1b: split W_ih into bf16 hi/lo.
// ---------------------------------------------------------------------------
__global__ void wconv_kernel(const float* __restrict__ W) {
    const int idx = blockIdx.x * 256 + threadIdx.x;
    if (idx < GATES * K_DIM) {
        split_bf16(W[idx], g_Bhi[idx], g_Blo[idx]);
    }
}

// ---------------------------------------------------------------------------
// Kernel 2: x_proj = seq @ W_ih^T + bias via split-bf16 HMMA.
// acc = Ahi*Bhi + Ahi*Blo + Alo*Bhi  (fp32 accumulate; lo*lo dropped ~2^-16).
// BM=128, BN=128, BK=16; 256 threads, warp tile 32x64.
// 3-stage cp.async pipeline (48 KB smem), grid: n fastest for A-tile L2 reuse.
// ---------------------------------------------------------------------------
__device__ __forceinline__ void cp16(void* dst, const void* src) {
    const uint32_t d = (uint32_t)__cvta_generic_to_shared(dst);
    asm volatile("cp.async.cg.shared.global [%0], [%1], 16;\n" :: "r"(d), "l"(src));
}
__device__ __forceinline__ void ldsm4(uint32_t* r, const __nv_bfloat16* p) {
    const uint32_t a = (uint32_t)__cvta_generic_to_shared(p);
    asm volatile("ldmatrix.sync.aligned.m8n8.x4.shared.b16 {%0,%1,%2,%3}, [%4];"
                 : "=r"(r[0]), "=r"(r[1]), "=r"(r[2]), "=r"(r[3]) : "r"(a));
}
__device__ __forceinline__ void mma16816(float* c, const uint32_t* a, uint32_t b0, uint32_t b1) {
    asm volatile("mma.sync.aligned.m16n8k16.row.col.f32.bf16.bf16.f32 "
                 "{%0,%1,%2,%3}, {%4,%5,%6,%7}, {%8,%9}, {%0,%1,%2,%3};"
                 : "+f"(c[0]), "+f"(c[1]), "+f"(c[2]), "+f"(c[3])
                 : "r"(a[0]), "r"(a[1]), "r"(a[2]), "r"(a[3]), "r"(b0), "r"(b1));
}

#define NIT (K_DIM / 16)   // 134

__global__ __launch_bounds__(256, 1) void gemm_kernel(
    const float* __restrict__ b_ih,
    const float* __restrict__ b_hh)
{
    // [stage][hi/lo][128 rows x 16 cols], swizzled 16B chunks. 48 KB total.
    __shared__ __align__(128) __nv_bfloat16 sA[3][2][128 * 16];
    __shared__ __align__(128) __nv_bfloat16 sB[3][2][128 * 16];

    const int tid = threadIdx.x;
    const int bn = blockIdx.x * 128;   // n fastest -> 4 blocks sharing A-tile co-resident
    const int bm = blockIdx.y * 128;

    // --- prefetch addressing (1 x 16B chunk per thread per array per stage) ---
    const int prow = tid >> 1;                 // 0..127
    const int pch  = tid & 1;                  // logical chunk
    const int psc  = pch ^ ((prow >> 2) & 1);  // physical (swizzled) chunk
    const int psoff = prow * 16 + psc * 8;     // bf16 elems
    const size_t aoff = (size_t)(bm + prow) * K_DIM + pch * 8;
    const size_t boff = (size_t)(bn + prow) * K_DIM + pch * 8;

    // --- ldmatrix addressing (per-iter invariant) ---
    const int lane = tid & 31;
    const int warp = tid >> 5;
    const int wm = warp >> 1;                  // 0..3  (m: wm*32)
    const int wn = warp & 1;                   // 0..1  (n: wn*64)
    int aoffs[2];
#pragma unroll
    for (int mf = 0; mf < 2; ++mf) {
        const int r = wm * 32 + mf * 16 + (lane & 15);
        const int c = lane >> 4;
        aoffs[mf] = r * 16 + (c ^ ((r >> 2) & 1)) * 8;
    }
    int boffs[4];
#pragma unroll
    for (int ng = 0; ng < 4; ++ng) {
        const int r = wn * 64 + ng * 16 + ((lane & 7) | ((lane >> 4) << 3));
        const int c = (lane >> 3) & 1;
        boffs[ng] = r * 16 + (c ^ ((r >> 2) & 1)) * 8;
    }

    float acc[2][8][4];
#pragma unroll
    for (int mf = 0; mf < 2; ++mf)
#pragma unroll
        for (int n8 = 0; n8 < 8; ++n8)
#pragma unroll
            for (int q = 0; q < 4; ++q) acc[mf][n8][q] = 0.f;

    // prefetch stages 0,1
#pragma unroll
    for (int p = 0; p < 2; ++p) {
        const size_t kk = (size_t)p * 16;
        cp16(&sA[p][0][psoff], g_Ahi + aoff + kk);
        cp16(&sA[p][1][psoff], g_Alo + aoff + kk);
        cp16(&sB[p][0][psoff], g_Bhi + boff + kk);
        cp16(&sB[p][1][psoff], g_Blo + boff + kk);
        asm volatile("cp.async.commit_group;\n" ::);
    }

    int st = 0;   // stage of current iter
    for (int it = 0; it < NIT; ++it) {
        asm volatile("cp.async.wait_group 1;\n" ::);
        __syncthreads();

        // prefetch it+2 into stage (st+2)%3 (consumed two iters ago; all warps synced)
        if (it + 2 < NIT) {
            const int ns = (st + 2 >= 3) ? st - 1 : st + 2;
            const size_t kk = (size_t)(it + 2) * 16;
            cp16(&sA[ns][0][psoff], g_Ahi + aoff + kk);
            cp16(&sA[ns][1][psoff], g_Alo + aoff + kk);
            cp16(&sB[ns][0][psoff], g_Bhi + boff + kk);
            cp16(&sB[ns][1][psoff], g_Blo + boff + kk);
        }
        asm volatile("cp.async.commit_group;\n" ::);

        uint32_t ahi[2][4], alo[2][4], bhi[4][4], blo[4][4];
#pragma unroll
        for (int mf = 0; mf < 2; ++mf) {
            ldsm4(ahi[mf], &sA[st][0][aoffs[mf]]);
            ldsm4(alo[mf], &sA[st][1][aoffs[mf]]);
        }
#pragma unroll
        for (int ng = 0; ng < 4; ++ng) {
            ldsm4(bhi[ng], &sB[st][0][boffs[ng]]);
            ldsm4(blo[ng], &sB[st][1][boffs[ng]]);
        }
#pragma unroll
        for (int mf = 0; mf < 2; ++mf)
#pragma unroll
            for (int ng = 0; ng < 4; ++ng)
#pragma unroll
                for (int h = 0; h < 2; ++h) {
                    float* c = acc[mf][ng * 2 + h];
                    mma16816(c, ahi[mf], bhi[ng][2 * h], bhi[ng][2 * h + 1]);
                    mma16816(c, ahi[mf], blo[ng][2 * h], blo[ng][2 * h + 1]);
                    mma16816(c, alo[mf], bhi[ng][2 * h], bhi[ng][2 * h + 1]);
                }
        __syncthreads();
        st = (st == 2) ? 0 : st + 1;
    }

    // epilogue: c-frag lane mapping (m = l/4 (+8), n = 2*(l%4) (+1))
    const int qr = lane >> 2;
    const int qc = (lane & 3) * 2;
#pragma unroll
    for (int mf = 0; mf < 2; ++mf) {
#pragma unroll
        for (int n8 = 0; n8 < 8; ++n8) {
            const int m0 = bm + wm * 32 + mf * 16 + qr;
            const int n0 = bn + wn * 64 + n8 * 8 + qc;
            const float bias0 = b_ih[n0] + b_hh[n0];
            const float bias1 = b_ih[n0 + 1] + b_hh[n0 + 1];
            const float* c = acc[mf][n8];
            g_xproj[(size_t)m0 * GATES + n0]           = c[0] + bias0;
            g_xproj[(size_t)m0 * GATES + n0 + 1]       = c[1] + bias1;
            g_xproj[(size_t)(m0 + 8) * GATES + n0]     = c[2] + bias0;
            g_xproj[(size_t)(m0 + 8) * GATES + n0 + 1] = c[3] + bias1;
        }
    }
}

// ---------------------------------------------------------------------------
// Kernel 3: LSTM recurrence. 148 blocks: 104 x 3 seqs + 44 x 2 seqs.
// Thread g computes gate row g for up to 3 sequences; xproj for step s+1 is
// prefetched during step s. Activations via __expf (overflow-safe forms).
// ---------------------------------------------------------------------------
__device__ __forceinline__ float fsig(float x) {
    const float z = __expf(-fabsf(x));
    const float p = __fdividef(1.f, 1.f + z);
    return x >= 0.f ? p : 1.f - p;
}
__device__ __forceinline__ float ftanh_(float x) {
    const float t = __expf(-2.f * fabsf(x));
    const float r = __fdividef(1.f - t, 1.f + t);
    return x >= 0.f ? r : -r;
}

__global__ __launch_bounds__(512, 1) void lstm_kernel(
    const float* __restrict__ Whh,
    float* __restrict__ out)
{
    __shared__ float h_sh[3 * 128];
    __shared__ float gates_sh[3 * 512];

    const int tid = threadIdx.x;
    const int blk = blockIdx.x;
    int n0, ns;
    if (blk < 104) { n0 = 3 * blk; ns = 3; }
    else           { n0 = 312 + 2 * (blk - 104); ns = 2; }

    // Register-cache lower 64 recurrent weights of this gate row.
    float wreg[64];
    {
        const float4* wp = (const float4*)(Whh + tid * 128);
#pragma unroll
        for (int i = 0; i < 16; i++) {
            const float4 t = wp[i];
            wreg[i * 4 + 0] = t.x; wreg[i * 4 + 1] = t.y;
            wreg[i * 4 + 2] = t.z; wreg[i * 4 + 3] = t.w;
        }
    }
    const float* __restrict__ wgu = Whh + tid * 128 + 64;  // upper half (L1-resident)

    if (tid < 384) h_sh[tid] = 0.f;    // covers 3*128; seq 2 slot stays 0 for ns==2
    const int sq = tid >> 7;           // 0..3
    const int j  = tid & 127;
    const int active = (sq < ns);
    float creg = 0.f;
    const int n_pw = n0 + (active ? sq : 0);
    const int bb = n_pw / 25;
    const int vv = n_pw % 25;
    const long outbase = ((long)(bb * 128 + j) * 50) * 25 + vv;

    // prefetch step 0
    float xp0 = g_xproj[(size_t)((n0 + 0) * 50 + 0) * GATES + tid];
    float xp1 = g_xproj[(size_t)((n0 + 1) * 50 + 0) * GATES + tid];
    float xp2 = (ns == 3) ? g_xproj[(size_t)((n0 + 2) * 50 + 0) * GATES + tid] : 0.f;
    __syncthreads();

    for (int s = 0; s < NSEG; s++) {
        // issue prefetch for step s+1 (consumed next iteration)
        float nx0 = 0.f, nx1 = 0.f, nx2 = 0.f;
        if (s + 1 < NSEG) {
            nx0 = g_xproj[(size_t)((n0 + 0) * 50 + s + 1) * GATES + tid];
            nx1 = g_xproj[(size_t)((n0 + 1) * 50 + s + 1) * GATES + tid];
            if (ns == 3) nx2 = g_xproj[(size_t)((n0 + 2) * 50 + s + 1) * GATES + tid];
        }

        float acc0 = xp0, acc1 = xp1, acc2 = xp2;
        // lower 64 k: weights in registers (h for seq2 reads zeros when ns==2)
#pragma unroll
        for (int k = 0; k < 64; k += 4) {
            const float4 h0 = *(const float4*)&h_sh[0 * 128 + k];
            const float4 h1 = *(const float4*)&h_sh[1 * 128 + k];
            const float4 h2 = *(const float4*)&h_sh[2 * 128 + k];
            const float w0 = wreg[k], w1 = wreg[k + 1], w2 = wreg[k + 2], w3 = wreg[k + 3];
            acc0 += w0 * h0.x + w1 * h0.y + w2 * h0.z + w3 * h0.w;
            acc1 += w0 * h1.x + w1 * h1.y + w2 * h1.z + w3 * h1.w;
            acc2 += w0 * h2.x + w1 * h2.y + w2 * h2.z + w3 * h2.w;
        }
        // upper 64 k: weights from L1/L2
#pragma unroll
        for (int k = 0; k < 64; k += 4) {
            const float4 w4 = *(const float4*)&wgu[k];
            const float4 h0 = *(const float4*)&h_sh[0 * 128 + 64 + k];
            const float4 h1 = *(const float4*)&h_sh[1 * 128 + 64 + k];
            const float4 h2 = *(const float4*)&h_sh[2 * 128 + 64 + k];
            acc0 += w4.x * h0.x + w4.y * h0.y + w4.z * h0.z + w4.w * h0.w;
            acc1 += w4.x * h1.x + w4.y * h1.y + w4.z * h1.z + w4.w * h1.w;
            acc2 += w4.x * h2.x + w4.y * h2.y + w4.z * h2.z + w4.w * h2.w;
        }
        gates_sh[0 * 512 + tid] = acc0;
        gates_sh[1 * 512 + tid] = acc1;
        gates_sh[2 * 512 + tid] = acc2;
        __syncthreads();

        // pointwise: gates layout [i | f | g | o], 128 each
        if (active) {
            const float gi = gates_sh[sq * 512 + j];
            const float gf = gates_sh[sq * 512 + 128 + j];
            const float gg = gates_sh[sq * 512 + 256 + j];
            const float go = gates_sh[sq * 512 + 384 + j];
            creg = fsig(gf) * creg + fsig(gi) * ftanh_(gg);
            const float h = fsig(go) * ftanh_(creg);
            h_sh[sq * 128 + j] = h;
            out[outbase + (long)s * 25] = h;   // out[b, j, s, v]
        }
        __syncthreads();
        xp0 = nx0; xp1 = nx1; xp2 = nx2;
    }
}

// ---------------------------------------------------------------------------
extern "C" void kernel_launch(void* const* d_in, const int* in_sizes, int n_in,
                              void* d_out, int out_size) {
    const float* x    = (const float*)d_in[0];  // (16,64,200,25)
    const float* W_ih = (const float*)d_in[1];  // (512,2144)
    const float* W_hh = (const float*)d_in[2];  // (512,128)
    const float* b_ih = (const float*)d_in[3];  // (512)
    const float* b_hh = (const float*)d_in[4];  // (512)
    float* out = (float*)d_out;                 // (16,128,50,25)
    (void)in_sizes; (void)n_in; (void)out_size;

    dim3 gl(NSEG, 16);
    logsig_kernel<<<gl, 256, 0, 0>>>(x);

    wconv_kernel<<<(GATES * K_DIM + 255) / 256, 256, 0, 0>>>(W_ih);

    dim3 gg(GATES / 128, M_PAD / 128);          // (4, 157): n fastest
    gemm_kernel<<<gg, 256, 0, 0>>>(b_ih, b_hh);

    lstm_kernel<<<148, 512, 0, 0>>>(W_hh, out);
}